// round 13
// baseline (speedup 1.0000x reference)
#include <cuda_runtime.h>
#include <cuda_bf16.h>
#include <cstdint>

#define B_ROWS 8192
#define DIM    128
#define BM     128
#define SH     136            // halves per smem bf16 row (272 B): LDSM conflict-free
#define NTILES 2080           // 64*65/2 upper-triangle tiles (incl. diagonal)
#define NCTA   296            // persistent CTAs: 2/SM on 148 SMs -> all co-resident
#define NVIRT  (NTILES + 64 * 2)   // phantom-weighted timeline (2 per converter CTA)
#define NEG_INF_F (-1e30f)
#define POS_INF_F ( 1e30f)
#define MARGIN_F  0.2f

// smem layout (dynamic): A | B0 | B1 | sRow ; sCol aliases B[p]
#define AB_BYTES   (BM * SH * 2)                   // 34816
#define B_OFF(p)   (AB_BYTES + (p) * AB_BYTES)
#define SROW_OFF   (3 * AB_BYTES)                  // 104448
#define SMEM_TOTAL (SROW_OFF + 8 * BM * 8)         // 112640

// ---------------- device-global state ----------------
__device__ unsigned       g_max_enc[B_ROWS];
__device__ unsigned       g_min_enc[B_ROWS];
__device__ __nv_bfloat16  g_im_bf16[B_ROWS * DIM];   // 2 MB, L2-resident
__device__ int            g_ids32[B_ROWS];
__device__ int            g_flags[64];               // block-converted flags (reset by last CTA)
__device__ int            g_done;                    // CTA completion counter (reset by last CTA)

__device__ __forceinline__ unsigned enc_f(float f) {
    unsigned u = __float_as_uint(f);
    return (u & 0x80000000u) ? ~u : (u | 0x80000000u);
}
__device__ __forceinline__ float dec_f(unsigned u) {
    return __uint_as_float((u & 0x80000000u) ? (u & 0x7FFFFFFFu) : ~u);
}
__device__ __forceinline__ uint32_t smem_u32(const void* p) {
    uint32_t a;
    asm("{ .reg .u64 t; cvta.to.shared.u64 t, %1; cvt.u32.u64 %0, t; }" : "=r"(a) : "l"(p));
    return a;
}
__device__ __forceinline__ void wait_flag(int b) {
    volatile int* f = g_flags + b;
    while (*f == 0) __nanosleep(64);
}
#define LDSM_X4(r0, r1, r2, r3, addr) \
    asm volatile("ldmatrix.sync.aligned.m8n8.x4.shared.b16 {%0,%1,%2,%3}, [%4];" \
                 : "=r"(r0), "=r"(r1), "=r"(r2), "=r"(r3) : "r"(addr))
#define CP_ASYNC16(dst, src) \
    asm volatile("cp.async.cg.shared.global [%0], [%1], 16;" :: "r"(dst), "l"(src))
#define CP_COMMIT() asm volatile("cp.async.commit_group;" ::: "memory")
#define CP_WAIT0()  asm volatile("cp.async.wait_group 0;" ::: "memory")

// virtual boundary -> tile index (converter CTAs carry 2 phantom tiles each)
__device__ __forceinline__ int chunk_bound(int c) {
    int v = (int)(((long long)c * NVIRT) / NCTA);
    int conv = c < 64 ? c : 64;
    return v - 2 * conv;
}

// ---------------------------------------------------------------------------
// Single fused persistent kernel: convert (CTAs 0..63) + tiles + finalize.
// Mainloop/epilogue math identical to R12 (47.6us proven).
// ---------------------------------------------------------------------------
__global__ void __launch_bounds__(256, 2)
tile_kernel(const float* __restrict__ im, const void* __restrict__ ids,
            float* __restrict__ out) {
    extern __shared__ char smem[];
    __shared__ int s_idr[BM], s_idc[BM];
    __shared__ int s_is64;
    __shared__ bool s_last;
    const int tid = threadIdx.x;
    const int cta = blockIdx.x;
    const uint32_t smem_base = smem_u32(smem);

    // ---- phase 1: converters (CTAs 0..63) ----
    if (cta < 64) {
        if (tid < 32) {
            // SAFE dtype detection: odd words 1..129 (in bounds either dtype)
            const unsigned* w = (const unsigned*)ids;
            unsigned v = w[2 * tid + 1] | w[2 * tid + 65];
            unsigned any = __ballot_sync(0xffffffffu, v != 0u);
            if (tid == 0) s_is64 = (any == 0u) ? 1 : 0;
        }
        __syncthreads();
        const int base = cta * BM;
        if (tid < BM) {
            int idv = s_is64 ? (int)((const long long*)ids)[base + tid]
                             : ((const int*)ids)[base + tid];
            g_ids32[base + tid] = idv;
            g_max_enc[base + tid] = enc_f(NEG_INF_F);
            g_min_enc[base + tid] = enc_f(POS_INF_F);
        }
        const float4* src = (const float4*)im + base * 32;   // 32 float4 per row
        __nv_bfloat162* dstb = (__nv_bfloat162*)(g_im_bf16 + (size_t)base * DIM);
#pragma unroll
        for (int it = 0; it < 16; ++it) {
            int idx = it * 256 + tid;                        // 0..4095
            float4 v = src[idx];
            dstb[2 * idx + 0] = __floats2bfloat162_rn(v.x, v.y);
            dstb[2 * idx + 1] = __floats2bfloat162_rn(v.z, v.w);
        }
        __threadfence();
        __syncthreads();
        if (tid == 0) atomicExch(&g_flags[cta], 1);
    }

    // ---- phase 2: tile chunk ----
    const int t0 = chunk_bound(cta);
    const int t1 = chunk_bound(cta + 1);

    // coords of tile t0 (lexicographic upper triangle incl. diagonal)
    int bi = (int)((129.0f - sqrtf(16641.0f - 8.0f * (float)t0)) * 0.5f);
    if (bi < 0) bi = 0;
    if (bi > 63) bi = 63;
    while (bi > 0 && 64 * bi - bi * (bi - 1) / 2 > t0) --bi;
    while (64 * (bi + 1) - (bi + 1) * bi / 2 <= t0) ++bi;
    int bj = bi + (t0 - (64 * bi - bi * (bi - 1) / 2));

#define STAGE(dstoff, row0) do {                                              \
        uint32_t _d = smem_base + (dstoff);                                   \
        const char* _s = (const char*)(g_im_bf16 + (size_t)(row0) * DIM);     \
        _Pragma("unroll")                                                     \
        for (int _it = 0; _it < 8; ++_it) {                                   \
            int _idx = _it * 256 + tid;                                       \
            int _row = _idx >> 4, _q = _idx & 15;                             \
            CP_ASYNC16(_d + _row * (SH * 2) + _q * 16, _s + _row * 256 + _q * 16); \
        } } while (0)

    if (t0 < t1) {
        if (tid == 0) wait_flag(bi);
        if (tid == 1) wait_flag(bj);
        __syncthreads();
        STAGE(0, bi * BM);          // A
        STAGE(B_OFF(0), bj * BM);   // B(t0)
        CP_COMMIT();
    }

    const int warp = tid >> 5, lane = tid & 31;
    const int wm = warp >> 1, wn = warp & 1;
    const int g = lane >> 2, tig = lane & 3;
    const int grp = lane >> 3, rin = lane & 7;

    uint32_t aaddr[2];
#pragma unroll
    for (int mt = 0; mt < 2; ++mt)
        aaddr[mt] = smem_base + 2 * ((wm * 32 + mt * 16 + (grp & 1) * 8 + rin) * SH + (grp >> 1) * 8);

    int p = 0;
    for (int t = t0; t < t1; ++t, p ^= 1) {
        const int m0 = bi * BM, n0 = bj * BM;
        const bool diag = (bi == bj);
        int nbi = bi, nbj = bj + 1;
        if (nbj == 64) { ++nbi; nbj = nbi; }

        CP_WAIT0();                              // tile data landed
        if (tid < BM) {
            s_idr[tid] = g_ids32[m0 + tid];
            s_idc[tid] = g_ids32[n0 + tid];
        }
        if (t + 1 < t1) {                        // gate next tile's source blocks
            if (tid == 0) wait_flag(nbi);
            if (tid == 1) wait_flag(nbj);
        }
        __syncthreads();

        const uint32_t Bs32 = smem_base + B_OFF(p);
        uint32_t baddr[4];
#pragma unroll
        for (int q = 0; q < 4; ++q)
            baddr[q] = Bs32 + 2 * ((wn * 64 + 16 * q + (grp >> 1) * 8 + rin) * SH + (grp & 1) * 8);

        float acc[2][8][4];
#pragma unroll
        for (int mt = 0; mt < 2; ++mt)
#pragma unroll
            for (int nt = 0; nt < 8; ++nt)
#pragma unroll
                for (int r = 0; r < 4; ++r) acc[mt][nt][r] = 0.0f;

#pragma unroll
        for (int ks = 0; ks < 8; ++ks) {
            const uint32_t koff = ks * 32;
            unsigned a[2][4], b[8][2];
#pragma unroll
            for (int mt = 0; mt < 2; ++mt)
                LDSM_X4(a[mt][0], a[mt][1], a[mt][2], a[mt][3], aaddr[mt] + koff);
#pragma unroll
            for (int q = 0; q < 4; ++q)
                LDSM_X4(b[2 * q][0], b[2 * q][1], b[2 * q + 1][0], b[2 * q + 1][1], baddr[q] + koff);
#pragma unroll
            for (int mt = 0; mt < 2; ++mt)
#pragma unroll
                for (int nt = 0; nt < 8; ++nt) {
                    asm volatile(
                        "mma.sync.aligned.m16n8k16.row.col.f32.bf16.bf16.f32 "
                        "{%0,%1,%2,%3}, {%4,%5,%6,%7}, {%8,%9}, {%0,%1,%2,%3};"
                        : "+f"(acc[mt][nt][0]), "+f"(acc[mt][nt][1]),
                          "+f"(acc[mt][nt][2]), "+f"(acc[mt][nt][3])
                        : "r"(a[mt][0]), "r"(a[mt][1]), "r"(a[mt][2]), "r"(a[mt][3]),
                          "r"(b[nt][0]), "r"(b[nt][1]));
                }
        }
        __syncthreads();                         // done reading A and B[p]

        if (t + 1 < t1) {                        // prefetch next tile
            if (nbi != bi) STAGE(0, nbi * BM);
            STAGE(B_OFF(1 - p), nbj * BM);
            CP_COMMIT();
        }

        // ---- register-pooled epilogue (exact R9/R12 math); sCol aliases B[p] ----
        float2* sRow = (float2*)(smem + SROW_OFF);
        float2* sCol = (float2*)(smem + B_OFF(p));

        int rids[4];
#pragma unroll
        for (int mt = 0; mt < 2; ++mt)
#pragma unroll
            for (int half = 0; half < 2; ++half)
                rids[mt * 2 + half] = s_idr[wm * 32 + mt * 16 + g + half * 8];

        float rmin[4] = {POS_INF_F, POS_INF_F, POS_INF_F, POS_INF_F};
        float rmax[4] = {NEG_INF_F, NEG_INF_F, NEG_INF_F, NEG_INF_F};

#pragma unroll
        for (int ph = 0; ph < 2; ++ph) {
            float cmin[8], cmax[8];
            int cids[8];
#pragma unroll
            for (int i = 0; i < 8; ++i) {
                cmin[i] = POS_INF_F; cmax[i] = NEG_INF_F;
                int nt = ph * 4 + (i >> 1);
                cids[i] = s_idc[wn * 64 + nt * 8 + 2 * tig + (i & 1)];
            }
#pragma unroll
            for (int i = 0; i < 8; ++i) {
                const int nt = ph * 4 + (i >> 1), e = i & 1;
                const int lc = wn * 64 + nt * 8 + 2 * tig + e;
                const int cid = cids[i];
#pragma unroll
                for (int mt = 0; mt < 2; ++mt)
#pragma unroll
                    for (int half = 0; half < 2; ++half) {
                        const int ri = mt * 2 + half;
                        float s = acc[mt][nt][half * 2 + e];
                        if (diag && (wm * 32 + mt * 16 + g + half * 8) == lc) s = 0.0f;
                        if (rids[ri] == cid) {
                            rmin[ri] = fminf(rmin[ri], s);
                            cmin[i]  = fminf(cmin[i], s);
                        } else {
                            rmax[ri] = fmaxf(rmax[ri], s);
                            cmax[i]  = fmaxf(cmax[i], s);
                        }
                    }
            }
            if (!diag) {
                const int slot = wm * 8 + g;
#pragma unroll
                for (int i = 0; i < 8; ++i) {
                    const int nt = ph * 4 + (i >> 1);
                    const int lc = wn * 64 + nt * 8 + 2 * tig + (i & 1);
                    sCol[slot * BM + lc] = make_float2(cmin[i], cmax[i]);
                }
            }
        }
        {
            const int slot = wn * 4 + tig;
#pragma unroll
            for (int ri = 0; ri < 4; ++ri) {
                const int lr = wm * 32 + (ri >> 1) * 16 + g + (ri & 1) * 8;
                sRow[slot * BM + lr] = make_float2(rmin[ri], rmax[ri]);
            }
        }
        __syncthreads();

        if (tid < BM) {
            float vmin = POS_INF_F, vmax = NEG_INF_F;
#pragma unroll
            for (int s = 0; s < 8; ++s) {
                float2 q = sRow[s * BM + tid];
                vmin = fminf(vmin, q.x);
                vmax = fmaxf(vmax, q.y);
            }
            atomicMax(&g_max_enc[m0 + tid], enc_f(vmax));
            atomicMin(&g_min_enc[m0 + tid], enc_f(vmin));
        } else if (!diag) {
            const int c = tid - BM;
            float vmin = POS_INF_F, vmax = NEG_INF_F;
#pragma unroll
            for (int s = 0; s < 32; ++s) {
                float2 q = sCol[s * BM + c];
                vmin = fminf(vmin, q.x);
                vmax = fmaxf(vmax, q.y);
            }
            atomicMax(&g_max_enc[n0 + c], enc_f(vmax));
            atomicMin(&g_min_enc[n0 + c], enc_f(vmin));
        }
        __syncthreads();                         // partials free; ids may be rewritten

        bi = nbi; bj = nbj;
    }
#undef STAGE

    // ---- phase 3: fused finalize (last CTA) ----
    __threadfence();
    __syncthreads();
    if (tid == 0) s_last = (atomicAdd(&g_done, 1) == NCTA - 1);
    __syncthreads();
    if (s_last) {
        __threadfence();
        float* part = (float*)(smem + SROW_OFF);
        float s = 0.0f;
        for (int i = tid; i < B_ROWS; i += 256)
            s += fmaxf(MARGIN_F + dec_f(g_max_enc[i]) - dec_f(g_min_enc[i]), 0.0f);
        part[tid] = s;
        __syncthreads();
        for (int o = 128; o; o >>= 1) {
            if (tid < o) part[tid] += part[tid + o];
            __syncthreads();
        }
        if (tid < 64) g_flags[tid] = 0;          // reset for next graph replay
        if (tid == 0) {
            out[0] = part[0];
            g_done = 0;
        }
    }
}

extern "C" void kernel_launch(void* const* d_in, const int* in_sizes, int n_in,
                              void* d_out, int out_size) {
    const float* im  = (const float*)d_in[0];
    const void*  ids = d_in[1];

    cudaFuncSetAttribute(tile_kernel, cudaFuncAttributeMaxDynamicSharedMemorySize, SMEM_TOTAL);

    tile_kernel<<<NCTA, 256, SMEM_TOTAL>>>(im, ids, (float*)d_out);
}

// round 14
// speedup vs baseline: 1.0464x; 1.0464x over previous
#include <cuda_runtime.h>
#include <cuda_bf16.h>
#include <cstdint>

#define B_ROWS 8192
#define DIM    128
#define BM     128
#define SH     136            // halves per smem bf16 row (272 B): LDSM conflict-free
#define NTILES 2080           // 64*65/2 upper-triangle tiles (incl. diagonal)
#define NCTA   296            // persistent CTAs: 2/SM on 148 SMs
#define NEG_INF_F (-1e30f)
#define POS_INF_F ( 1e30f)
#define MARGIN_F  0.2f

// smem layout (dynamic): A | B0 | B1 | sRow ; sCol aliases B[p]
#define AB_BYTES   (BM * SH * 2)                   // 34816
#define B_OFF(p)   (AB_BYTES + (p) * AB_BYTES)
#define SROW_OFF   (3 * AB_BYTES)                  // 104448
#define SMEM_TOTAL (SROW_OFF + 8 * BM * 8)         // 112640

// ---------------- device-global state ----------------
__device__ unsigned       g_max_enc[B_ROWS];
__device__ unsigned       g_min_enc[B_ROWS];
__device__ __nv_bfloat16  g_im_bf16[B_ROWS * DIM];   // 2 MB, L2-resident
__device__ int            g_ids32[B_ROWS];
__device__ int            g_ctr = NCTA;              // dynamic tile counter (self-resetting)
__device__ int            g_done = 0;                // CTA completion counter (self-resetting)

__device__ __forceinline__ unsigned enc_f(float f) {
    unsigned u = __float_as_uint(f);
    return (u & 0x80000000u) ? ~u : (u | 0x80000000u);
}
__device__ __forceinline__ float dec_f(unsigned u) {
    return __uint_as_float((u & 0x80000000u) ? (u & 0x7FFFFFFFu) : ~u);
}
__device__ __forceinline__ uint32_t smem_u32(const void* p) {
    uint32_t a;
    asm("{ .reg .u64 t; cvta.to.shared.u64 t, %1; cvt.u32.u64 %0, t; }" : "=r"(a) : "l"(p));
    return a;
}
// lexicographic upper-triangle coords: S(b) = 64b - b(b-1)/2
__device__ __forceinline__ void tile_coords(int t, int& bi, int& bj) {
    int b = (int)((129.0f - sqrtf(16641.0f - 8.0f * (float)t)) * 0.5f);
    if (b < 0) b = 0;
    if (b > 63) b = 63;
    while (b > 0 && 64 * b - b * (b - 1) / 2 > t) --b;
    while (64 * (b + 1) - (b + 1) * b / 2 <= t) ++b;
    bi = b;
    bj = b + (t - (64 * b - b * (b - 1) / 2));
}
#define LDSM_X4(r0, r1, r2, r3, addr) \
    asm volatile("ldmatrix.sync.aligned.m8n8.x4.shared.b16 {%0,%1,%2,%3}, [%4];" \
                 : "=r"(r0), "=r"(r1), "=r"(r2), "=r"(r3) : "r"(addr))
#define CP_ASYNC16(dst, src) \
    asm volatile("cp.async.cg.shared.global [%0], [%1], 16;" :: "r"(dst), "l"(src))
#define CP_COMMIT() asm volatile("cp.async.commit_group;" ::: "memory")
#define CP_WAIT0()  asm volatile("cp.async.wait_group 0;" ::: "memory")

// ---------------------------------------------------------------------------
// Kernel 1: convert im -> bf16, ids -> int32, clear reductions (as R12).
// ---------------------------------------------------------------------------
__global__ void convert_kernel(const float* __restrict__ im, const void* __restrict__ ids) {
    __shared__ int s_is64;
    const int tid = blockIdx.x * blockDim.x + threadIdx.x;   // 65536

    if (blockIdx.x < 32) {
        if (threadIdx.x < 32) {
            const unsigned* w = (const unsigned*)ids;
            unsigned v = w[2 * threadIdx.x + 1] | w[2 * threadIdx.x + 65];
            unsigned any = __ballot_sync(0xffffffffu, v != 0u);
            if (threadIdx.x == 0) s_is64 = (any == 0u) ? 1 : 0;
        }
        __syncthreads();
        g_max_enc[tid] = enc_f(NEG_INF_F);
        g_min_enc[tid] = enc_f(POS_INF_F);
        g_ids32[tid] = s_is64 ? (int)((const long long*)ids)[tid]
                              : ((const int*)ids)[tid];
    }
    const float4* in4 = (const float4*)im;
    float4 v0 = in4[tid];
    float4 v1 = in4[tid + 65536];
    float4 v2 = in4[tid + 131072];
    float4 v3 = in4[tid + 196608];
    __nv_bfloat162* o = (__nv_bfloat162*)g_im_bf16;
    o[2 * tid + 0]            = __floats2bfloat162_rn(v0.x, v0.y);
    o[2 * tid + 1]            = __floats2bfloat162_rn(v0.z, v0.w);
    o[2 * (tid + 65536) + 0]  = __floats2bfloat162_rn(v1.x, v1.y);
    o[2 * (tid + 65536) + 1]  = __floats2bfloat162_rn(v1.z, v1.w);
    o[2 * (tid + 131072) + 0] = __floats2bfloat162_rn(v2.x, v2.y);
    o[2 * (tid + 131072) + 1] = __floats2bfloat162_rn(v2.z, v2.w);
    o[2 * (tid + 196608) + 0] = __floats2bfloat162_rn(v3.x, v3.y);
    o[2 * (tid + 196608) + 1] = __floats2bfloat162_rn(v3.z, v3.w);
}

// ---------------------------------------------------------------------------
// Kernel 2: persistent tiles with DYNAMIC scheduling (atomic counter),
// cp.async prefetch of next tile (A single-buffered, B double-buffered).
// Mainloop/epilogue math identical to R12 (47.6us proven).
// ---------------------------------------------------------------------------
__global__ void __launch_bounds__(256, 2)
tile_kernel(void) {
    extern __shared__ char smem[];
    __shared__ int s_idr[BM], s_idc[BM];
    __shared__ int s_next;
    const int tid = threadIdx.x;
    const uint32_t smem_base = smem_u32(smem);

    int bi, bj;
    tile_coords(blockIdx.x, bi, bj);          // first tile: static seed

#define STAGE(dstoff, row0) do {                                              \
        uint32_t _d = smem_base + (dstoff);                                   \
        const char* _s = (const char*)(g_im_bf16 + (size_t)(row0) * DIM);     \
        _Pragma("unroll")                                                     \
        for (int _it = 0; _it < 8; ++_it) {                                   \
            int _idx = _it * 256 + tid;                                       \
            int _row = _idx >> 4, _q = _idx & 15;                             \
            CP_ASYNC16(_d + _row * (SH * 2) + _q * 16, _s + _row * 256 + _q * 16); \
        } } while (0)

    STAGE(0, bi * BM);          // A
    STAGE(B_OFF(0), bj * BM);   // B
    CP_COMMIT();

    const int warp = tid >> 5, lane = tid & 31;
    const int wm = warp >> 1, wn = warp & 1;
    const int g = lane >> 2, tig = lane & 3;
    const int grp = lane >> 3, rin = lane & 7;

    uint32_t aaddr[2];
#pragma unroll
    for (int mt = 0; mt < 2; ++mt)
        aaddr[mt] = smem_base + 2 * ((wm * 32 + mt * 16 + (grp & 1) * 8 + rin) * SH + (grp >> 1) * 8);

    int p = 0;
    for (;;) {
        const int m0 = bi * BM, n0 = bj * BM;
        const bool diag = (bi == bj);

        if (tid == 0) s_next = atomicAdd(&g_ctr, 1);   // grab next tile early
        CP_WAIT0();                                    // tile data landed
        if (tid < BM) {
            s_idr[tid] = g_ids32[m0 + tid];
            s_idc[tid] = g_ids32[n0 + tid];
        }
        __syncthreads();                               // ids + s_next + staged data visible
        const int tn = s_next;

        const uint32_t Bs32 = smem_base + B_OFF(p);
        uint32_t baddr[4];
#pragma unroll
        for (int q = 0; q < 4; ++q)
            baddr[q] = Bs32 + 2 * ((wn * 64 + 16 * q + (grp >> 1) * 8 + rin) * SH + (grp & 1) * 8);

        float acc[2][8][4];
#pragma unroll
        for (int mt = 0; mt < 2; ++mt)
#pragma unroll
            for (int nt = 0; nt < 8; ++nt)
#pragma unroll
                for (int r = 0; r < 4; ++r) acc[mt][nt][r] = 0.0f;

#pragma unroll
        for (int ks = 0; ks < 8; ++ks) {
            const uint32_t koff = ks * 32;
            unsigned a[2][4], b[8][2];
#pragma unroll
            for (int mt = 0; mt < 2; ++mt)
                LDSM_X4(a[mt][0], a[mt][1], a[mt][2], a[mt][3], aaddr[mt] + koff);
#pragma unroll
            for (int q = 0; q < 4; ++q)
                LDSM_X4(b[2 * q][0], b[2 * q][1], b[2 * q + 1][0], b[2 * q + 1][1], baddr[q] + koff);
#pragma unroll
            for (int mt = 0; mt < 2; ++mt)
#pragma unroll
                for (int nt = 0; nt < 8; ++nt) {
                    asm volatile(
                        "mma.sync.aligned.m16n8k16.row.col.f32.bf16.bf16.f32 "
                        "{%0,%1,%2,%3}, {%4,%5,%6,%7}, {%8,%9}, {%0,%1,%2,%3};"
                        : "+f"(acc[mt][nt][0]), "+f"(acc[mt][nt][1]),
                          "+f"(acc[mt][nt][2]), "+f"(acc[mt][nt][3])
                        : "r"(a[mt][0]), "r"(a[mt][1]), "r"(a[mt][2]), "r"(a[mt][3]),
                          "r"(b[nt][0]), "r"(b[nt][1]));
                }
        }
        __syncthreads();                         // done reading A and B[p]

        // prefetch next grabbed tile: A (single-buffered; epilogue doesn't read A)
        // and B into the alternate buffer.
        int nbi = bi, nbj = bj;
        if (tn < NTILES) {
            tile_coords(tn, nbi, nbj);
            STAGE(0, nbi * BM);
            STAGE(B_OFF(1 - p), nbj * BM);
            CP_COMMIT();
        }

        // ---- register-pooled epilogue (exact R12 math); sCol aliases B[p] ----
        float2* sRow = (float2*)(smem + SROW_OFF);
        float2* sCol = (float2*)(smem + B_OFF(p));

        int rids[4];
#pragma unroll
        for (int mt = 0; mt < 2; ++mt)
#pragma unroll
            for (int half = 0; half < 2; ++half)
                rids[mt * 2 + half] = s_idr[wm * 32 + mt * 16 + g + half * 8];

        float rmin[4] = {POS_INF_F, POS_INF_F, POS_INF_F, POS_INF_F};
        float rmax[4] = {NEG_INF_F, NEG_INF_F, NEG_INF_F, NEG_INF_F};

#pragma unroll
        for (int ph = 0; ph < 2; ++ph) {
            float cmin[8], cmax[8];
            int cids[8];
#pragma unroll
            for (int i = 0; i < 8; ++i) {
                cmin[i] = POS_INF_F; cmax[i] = NEG_INF_F;
                int nt = ph * 4 + (i >> 1);
                cids[i] = s_idc[wn * 64 + nt * 8 + 2 * tig + (i & 1)];
            }
#pragma unroll
            for (int i = 0; i < 8; ++i) {
                const int nt = ph * 4 + (i >> 1), e = i & 1;
                const int lc = wn * 64 + nt * 8 + 2 * tig + e;
                const int cid = cids[i];
#pragma unroll
                for (int mt = 0; mt < 2; ++mt)
#pragma unroll
                    for (int half = 0; half < 2; ++half) {
                        const int ri = mt * 2 + half;
                        float s = acc[mt][nt][half * 2 + e];
                        if (diag && (wm * 32 + mt * 16 + g + half * 8) == lc) s = 0.0f;
                        if (rids[ri] == cid) {
                            rmin[ri] = fminf(rmin[ri], s);
                            cmin[i]  = fminf(cmin[i], s);
                        } else {
                            rmax[ri] = fmaxf(rmax[ri], s);
                            cmax[i]  = fmaxf(cmax[i], s);
                        }
                    }
            }
            if (!diag) {
                const int slot = wm * 8 + g;
#pragma unroll
                for (int i = 0; i < 8; ++i) {
                    const int nt = ph * 4 + (i >> 1);
                    const int lc = wn * 64 + nt * 8 + 2 * tig + (i & 1);
                    sCol[slot * BM + lc] = make_float2(cmin[i], cmax[i]);
                }
            }
        }
        {
            const int slot = wn * 4 + tig;
#pragma unroll
            for (int ri = 0; ri < 4; ++ri) {
                const int lr = wm * 32 + (ri >> 1) * 16 + g + (ri & 1) * 8;
                sRow[slot * BM + lr] = make_float2(rmin[ri], rmax[ri]);
            }
        }
        __syncthreads();

        if (tid < BM) {
            float vmin = POS_INF_F, vmax = NEG_INF_F;
#pragma unroll
            for (int s = 0; s < 8; ++s) {
                float2 q = sRow[s * BM + tid];
                vmin = fminf(vmin, q.x);
                vmax = fmaxf(vmax, q.y);
            }
            atomicMax(&g_max_enc[m0 + tid], enc_f(vmax));
            atomicMin(&g_min_enc[m0 + tid], enc_f(vmin));
        } else if (!diag) {
            const int c = tid - BM;
            float vmin = POS_INF_F, vmax = NEG_INF_F;
#pragma unroll
            for (int s = 0; s < 32; ++s) {
                float2 q = sCol[s * BM + c];
                vmin = fminf(vmin, q.x);
                vmax = fmaxf(vmax, q.y);
            }
            atomicMax(&g_max_enc[n0 + c], enc_f(vmax));
            atomicMin(&g_min_enc[n0 + c], enc_f(vmin));
        }
        __syncthreads();                         // partials free; ids may be rewritten

        if (tn >= NTILES) break;
        bi = nbi; bj = nbj; p ^= 1;
    }
#undef STAGE

    // self-reset scheduler state for next graph replay (deterministic)
    if (tid == 0) {
        if (atomicAdd(&g_done, 1) == NCTA - 1) {
            g_ctr = NCTA;
            g_done = 0;
        }
    }
}

// ---------------------------------------------------------------------------
// Kernel 3: deterministic scalar reduction of the hinge loss.
// ---------------------------------------------------------------------------
__global__ void finalize_kernel(float* __restrict__ out) {
    __shared__ float part[1024];
    float s = 0.0f;
    for (int i = threadIdx.x; i < B_ROWS; i += 1024) {
        s += fmaxf(MARGIN_F + dec_f(g_max_enc[i]) - dec_f(g_min_enc[i]), 0.0f);
    }
    part[threadIdx.x] = s;
    __syncthreads();
    for (int o = 512; o; o >>= 1) {
        if (threadIdx.x < o) part[threadIdx.x] += part[threadIdx.x + o];
        __syncthreads();
    }
    if (threadIdx.x == 0) out[0] = part[0];
}

extern "C" void kernel_launch(void* const* d_in, const int* in_sizes, int n_in,
                              void* d_out, int out_size) {
    const float* im  = (const float*)d_in[0];
    const void*  ids = d_in[1];

    cudaFuncSetAttribute(tile_kernel, cudaFuncAttributeMaxDynamicSharedMemorySize, SMEM_TOTAL);

    convert_kernel<<<256, 256>>>(im, ids);
    tile_kernel<<<NCTA, 256, SMEM_TOTAL>>>();
    finalize_kernel<<<1, 1024>>>((float*)d_out);
}

// round 15
// speedup vs baseline: 1.1025x; 1.0536x over previous
#include <cuda_runtime.h>
#include <cuda_bf16.h>
#include <cstdint>

#define B_ROWS 8192
#define DIM    128
#define BM     128
#define SH     136            // halves per smem bf16 row (272 B): LDSM conflict-free
#define NTILES 2080           // 64*65/2 upper-triangle tiles (incl. diagonal)
#define NCTA   296            // persistent CTAs: 2/SM on 148 SMs
#define CHUNK  7              // static tiles per CTA (296*7 = 2072)
#define TEXTRA 2072           // first dynamically-served tile
#define NEXTRA 8              // leftover tiles served via atomic counter
#define NEG_INF_F (-1e30f)
#define POS_INF_F ( 1e30f)
#define MARGIN_F  0.2f

// smem layout (dynamic): A | B0 | B1 | sRow ; sCol aliases B[p]
#define AB_BYTES   (BM * SH * 2)                   // 34816
#define B_OFF(p)   (AB_BYTES + (p) * AB_BYTES)
#define SROW_OFF   (3 * AB_BYTES)                  // 104448
#define SMEM_TOTAL (SROW_OFF + 8 * BM * 8)         // 112640

// ---------------- device-global state ----------------
__device__ unsigned       g_max_enc[B_ROWS];
__device__ unsigned       g_min_enc[B_ROWS];
__device__ __nv_bfloat16  g_im_bf16[B_ROWS * DIM];   // 2 MB, L2-resident
__device__ int            g_ids32[B_ROWS];
__device__ int            g_extra = 0;               // tail-tile counter (self-resetting)
__device__ int            g_done  = 0;               // CTA completion counter (self-resetting)

__device__ __forceinline__ unsigned enc_f(float f) {
    unsigned u = __float_as_uint(f);
    return (u & 0x80000000u) ? ~u : (u | 0x80000000u);
}
__device__ __forceinline__ float dec_f(unsigned u) {
    return __uint_as_float((u & 0x80000000u) ? (u & 0x7FFFFFFFu) : ~u);
}
__device__ __forceinline__ uint32_t smem_u32(const void* p) {
    uint32_t a;
    asm("{ .reg .u64 t; cvta.to.shared.u64 t, %1; cvt.u32.u64 %0, t; }" : "=r"(a) : "l"(p));
    return a;
}
// lexicographic upper-triangle coords: S(b) = 64b - b(b-1)/2
__device__ __forceinline__ void tile_coords(int t, int& bi, int& bj) {
    int b = (int)((129.0f - sqrtf(16641.0f - 8.0f * (float)t)) * 0.5f);
    if (b < 0) b = 0;
    if (b > 63) b = 63;
    while (b > 0 && 64 * b - b * (b - 1) / 2 > t) --b;
    while (64 * (b + 1) - (b + 1) * b / 2 <= t) ++b;
    bi = b;
    bj = b + (t - (64 * b - b * (b - 1) / 2));
}
#define LDSM_X4(r0, r1, r2, r3, addr) \
    asm volatile("ldmatrix.sync.aligned.m8n8.x4.shared.b16 {%0,%1,%2,%3}, [%4];" \
                 : "=r"(r0), "=r"(r1), "=r"(r2), "=r"(r3) : "r"(addr))
#define CP_ASYNC16(dst, src) \
    asm volatile("cp.async.cg.shared.global [%0], [%1], 16;" :: "r"(dst), "l"(src))
#define CP_COMMIT() asm volatile("cp.async.commit_group;" ::: "memory")
#define CP_WAIT0()  asm volatile("cp.async.wait_group 0;" ::: "memory")

// ---------------------------------------------------------------------------
// Kernel 1: convert im -> bf16, ids -> int32, clear reductions (as R12).
// ---------------------------------------------------------------------------
__global__ void convert_kernel(const float* __restrict__ im, const void* __restrict__ ids) {
    __shared__ int s_is64;
    const int tid = blockIdx.x * blockDim.x + threadIdx.x;   // 65536

    if (blockIdx.x < 32) {
        if (threadIdx.x < 32) {
            const unsigned* w = (const unsigned*)ids;
            unsigned v = w[2 * threadIdx.x + 1] | w[2 * threadIdx.x + 65];
            unsigned any = __ballot_sync(0xffffffffu, v != 0u);
            if (threadIdx.x == 0) s_is64 = (any == 0u) ? 1 : 0;
        }
        __syncthreads();
        g_max_enc[tid] = enc_f(NEG_INF_F);
        g_min_enc[tid] = enc_f(POS_INF_F);
        g_ids32[tid] = s_is64 ? (int)((const long long*)ids)[tid]
                              : ((const int*)ids)[tid];
    }
    const float4* in4 = (const float4*)im;
    float4 v0 = in4[tid];
    float4 v1 = in4[tid + 65536];
    float4 v2 = in4[tid + 131072];
    float4 v3 = in4[tid + 196608];
    __nv_bfloat162* o = (__nv_bfloat162*)g_im_bf16;
    o[2 * tid + 0]            = __floats2bfloat162_rn(v0.x, v0.y);
    o[2 * tid + 1]            = __floats2bfloat162_rn(v0.z, v0.w);
    o[2 * (tid + 65536) + 0]  = __floats2bfloat162_rn(v1.x, v1.y);
    o[2 * (tid + 65536) + 1]  = __floats2bfloat162_rn(v1.z, v1.w);
    o[2 * (tid + 131072) + 0] = __floats2bfloat162_rn(v2.x, v2.y);
    o[2 * (tid + 131072) + 1] = __floats2bfloat162_rn(v2.z, v2.w);
    o[2 * (tid + 196608) + 0] = __floats2bfloat162_rn(v3.x, v3.y);
    o[2 * (tid + 196608) + 1] = __floats2bfloat162_rn(v3.z, v3.w);
}

// ---------------------------------------------------------------------------
// Kernel 2: persistent tiles. Static 7-tile chunks with A-reuse and
// double-buffered B prefetch (exact R12); the 8 leftover tiles are grabbed
// dynamically (early-grab at top of last-known tile keeps prefetch overlap).
// ---------------------------------------------------------------------------
__global__ void __launch_bounds__(256, 2)
tile_kernel(void) {
    extern __shared__ char smem[];
    __shared__ int s_idr[BM], s_idc[BM];
    __shared__ int s_next;
    const int tid = threadIdx.x;
    const uint32_t smem_base = smem_u32(smem);

    const int t0 = blockIdx.x * CHUNK;
    const int t1 = t0 + CHUNK;

    int bi, bj;
    tile_coords(t0, bi, bj);

#define STAGE(dstoff, row0) do {                                              \
        uint32_t _d = smem_base + (dstoff);                                   \
        const char* _s = (const char*)(g_im_bf16 + (size_t)(row0) * DIM);     \
        _Pragma("unroll")                                                     \
        for (int _it = 0; _it < 8; ++_it) {                                   \
            int _idx = _it * 256 + tid;                                       \
            int _row = _idx >> 4, _q = _idx & 15;                             \
            CP_ASYNC16(_d + _row * (SH * 2) + _q * 16, _s + _row * 256 + _q * 16); \
        } } while (0)

    STAGE(0, bi * BM);          // A
    STAGE(B_OFF(0), bj * BM);   // B(t0)
    CP_COMMIT();

    const int warp = tid >> 5, lane = tid & 31;
    const int wm = warp >> 1, wn = warp & 1;
    const int g = lane >> 2, tig = lane & 3;
    const int grp = lane >> 3, rin = lane & 7;

    uint32_t aaddr[2];
#pragma unroll
    for (int mt = 0; mt < 2; ++mt)
        aaddr[mt] = smem_base + 2 * ((wm * 32 + mt * 16 + (grp & 1) * 8 + rin) * SH + (grp >> 1) * 8);

    int t = t0;
    int p = 0;
    for (;;) {
        const int m0 = bi * BM, n0 = bj * BM;
        const bool diag = (bi == bj);
        const bool grabbing = (t >= t1 - 1);     // last static tile, or an extra

        if (grabbing && tid == 0) s_next = atomicAdd(&g_extra, 1);
        CP_WAIT0();                              // tile data landed
        if (tid < BM) {
            s_idr[tid] = g_ids32[m0 + tid];
            s_idc[tid] = g_ids32[n0 + tid];
        }
        __syncthreads();                         // ids + s_next + staged data visible

        int tn;                                  // next tile (-1 = none)
        if (!grabbing)       tn = t + 1;
        else if (s_next < NEXTRA) tn = TEXTRA + s_next;
        else                 tn = -1;

        const uint32_t Bs32 = smem_base + B_OFF(p);
        uint32_t baddr[4];
#pragma unroll
        for (int q = 0; q < 4; ++q)
            baddr[q] = Bs32 + 2 * ((wn * 64 + 16 * q + (grp >> 1) * 8 + rin) * SH + (grp & 1) * 8);

        float acc[2][8][4];
#pragma unroll
        for (int mt = 0; mt < 2; ++mt)
#pragma unroll
            for (int nt = 0; nt < 8; ++nt)
#pragma unroll
                for (int r = 0; r < 4; ++r) acc[mt][nt][r] = 0.0f;

#pragma unroll
        for (int ks = 0; ks < 8; ++ks) {
            const uint32_t koff = ks * 32;
            unsigned a[2][4], b[8][2];
#pragma unroll
            for (int mt = 0; mt < 2; ++mt)
                LDSM_X4(a[mt][0], a[mt][1], a[mt][2], a[mt][3], aaddr[mt] + koff);
#pragma unroll
            for (int q = 0; q < 4; ++q)
                LDSM_X4(b[2 * q][0], b[2 * q][1], b[2 * q + 1][0], b[2 * q + 1][1], baddr[q] + koff);
#pragma unroll
            for (int mt = 0; mt < 2; ++mt)
#pragma unroll
                for (int nt = 0; nt < 8; ++nt) {
                    asm volatile(
                        "mma.sync.aligned.m16n8k16.row.col.f32.bf16.bf16.f32 "
                        "{%0,%1,%2,%3}, {%4,%5,%6,%7}, {%8,%9}, {%0,%1,%2,%3};"
                        : "+f"(acc[mt][nt][0]), "+f"(acc[mt][nt][1]),
                          "+f"(acc[mt][nt][2]), "+f"(acc[mt][nt][3])
                        : "r"(a[mt][0]), "r"(a[mt][1]), "r"(a[mt][2]), "r"(a[mt][3]),
                          "r"(b[nt][0]), "r"(b[nt][1]));
                }
        }
        __syncthreads();                         // done reading A and B[p]

        // prefetch next tile (A only when its row changes — reuse otherwise)
        int nbi = bi, nbj = bj;
        if (tn >= 0) {
            tile_coords(tn, nbi, nbj);
            if (nbi != bi) STAGE(0, nbi * BM);
            STAGE(B_OFF(1 - p), nbj * BM);
            CP_COMMIT();
        }

        // ---- register-pooled epilogue (exact R12 math); sCol aliases B[p] ----
        float2* sRow = (float2*)(smem + SROW_OFF);
        float2* sCol = (float2*)(smem + B_OFF(p));

        int rids[4];
#pragma unroll
        for (int mt = 0; mt < 2; ++mt)
#pragma unroll
            for (int half = 0; half < 2; ++half)
                rids[mt * 2 + half] = s_idr[wm * 32 + mt * 16 + g + half * 8];

        float rmin[4] = {POS_INF_F, POS_INF_F, POS_INF_F, POS_INF_F};
        float rmax[4] = {NEG_INF_F, NEG_INF_F, NEG_INF_F, NEG_INF_F};

#pragma unroll
        for (int ph = 0; ph < 2; ++ph) {
            float cmin[8], cmax[8];
            int cids[8];
#pragma unroll
            for (int i = 0; i < 8; ++i) {
                cmin[i] = POS_INF_F; cmax[i] = NEG_INF_F;
                int nt = ph * 4 + (i >> 1);
                cids[i] = s_idc[wn * 64 + nt * 8 + 2 * tig + (i & 1)];
            }
#pragma unroll
            for (int i = 0; i < 8; ++i) {
                const int nt = ph * 4 + (i >> 1), e = i & 1;
                const int lc = wn * 64 + nt * 8 + 2 * tig + e;
                const int cid = cids[i];
#pragma unroll
                for (int mt = 0; mt < 2; ++mt)
#pragma unroll
                    for (int half = 0; half < 2; ++half) {
                        const int ri = mt * 2 + half;
                        float s = acc[mt][nt][half * 2 + e];
                        if (diag && (wm * 32 + mt * 16 + g + half * 8) == lc) s = 0.0f;
                        if (rids[ri] == cid) {
                            rmin[ri] = fminf(rmin[ri], s);
                            cmin[i]  = fminf(cmin[i], s);
                        } else {
                            rmax[ri] = fmaxf(rmax[ri], s);
                            cmax[i]  = fmaxf(cmax[i], s);
                        }
                    }
            }
            if (!diag) {
                const int slot = wm * 8 + g;
#pragma unroll
                for (int i = 0; i < 8; ++i) {
                    const int nt = ph * 4 + (i >> 1);
                    const int lc = wn * 64 + nt * 8 + 2 * tig + (i & 1);
                    sCol[slot * BM + lc] = make_float2(cmin[i], cmax[i]);
                }
            }
        }
        {
            const int slot = wn * 4 + tig;
#pragma unroll
            for (int ri = 0; ri < 4; ++ri) {
                const int lr = wm * 32 + (ri >> 1) * 16 + g + (ri & 1) * 8;
                sRow[slot * BM + lr] = make_float2(rmin[ri], rmax[ri]);
            }
        }
        __syncthreads();

        if (tid < BM) {
            float vmin = POS_INF_F, vmax = NEG_INF_F;
#pragma unroll
            for (int s = 0; s < 8; ++s) {
                float2 q = sRow[s * BM + tid];
                vmin = fminf(vmin, q.x);
                vmax = fmaxf(vmax, q.y);
            }
            atomicMax(&g_max_enc[m0 + tid], enc_f(vmax));
            atomicMin(&g_min_enc[m0 + tid], enc_f(vmin));
        } else if (!diag) {
            const int c = tid - BM;
            float vmin = POS_INF_F, vmax = NEG_INF_F;
#pragma unroll
            for (int s = 0; s < 32; ++s) {
                float2 q = sCol[s * BM + c];
                vmin = fminf(vmin, q.x);
                vmax = fmaxf(vmax, q.y);
            }
            atomicMax(&g_max_enc[n0 + c], enc_f(vmax));
            atomicMin(&g_min_enc[n0 + c], enc_f(vmin));
        }
        __syncthreads();                         // partials free; ids may be rewritten

        if (tn < 0) break;
        t = tn; bi = nbi; bj = nbj; p ^= 1;
    }
#undef STAGE

    // self-reset scheduler state for next graph replay (deterministic)
    if (tid == 0) {
        if (atomicAdd(&g_done, 1) == NCTA - 1) {
            g_extra = 0;
            g_done = 0;
        }
    }
}

// ---------------------------------------------------------------------------
// Kernel 3: deterministic scalar reduction of the hinge loss.
// ---------------------------------------------------------------------------
__global__ void finalize_kernel(float* __restrict__ out) {
    __shared__ float part[1024];
    float s = 0.0f;
    for (int i = threadIdx.x; i < B_ROWS; i += 1024) {
        s += fmaxf(MARGIN_F + dec_f(g_max_enc[i]) - dec_f(g_min_enc[i]), 0.0f);
    }
    part[threadIdx.x] = s;
    __syncthreads();
    for (int o = 512; o; o >>= 1) {
        if (threadIdx.x < o) part[threadIdx.x] += part[threadIdx.x + o];
        __syncthreads();
    }
    if (threadIdx.x == 0) out[0] = part[0];
}

extern "C" void kernel_launch(void* const* d_in, const int* in_sizes, int n_in,
                              void* d_out, int out_size) {
    const float* im  = (const float*)d_in[0];
    const void*  ids = d_in[1];

    cudaFuncSetAttribute(tile_kernel, cudaFuncAttributeMaxDynamicSharedMemorySize, SMEM_TOTAL);

    convert_kernel<<<256, 256>>>(im, ids);
    tile_kernel<<<NCTA, 256, SMEM_TOTAL>>>();
    finalize_kernel<<<1, 1024>>>((float*)d_out);
}

// round 16
// speedup vs baseline: 1.1924x; 1.0815x over previous
#include <cuda_runtime.h>
#include <cuda_bf16.h>
#include <cstdint>

#define B_ROWS 8192
#define DIM    128
#define BM     128
#define SH     136            // halves per smem bf16 row (272 B): LDSM conflict-free
#define NTILES 2080           // 64*65/2 upper-triangle tiles (incl. diagonal)
#define NCTA   304            // persistent CTAs: 2/SM on 152 SMs (GB300)
#define CHUNK  6              // static tiles per CTA (304*6 = 1824)
#define TEXTRA 1824           // first dynamically-served tile
#define NEXTRA 256            // leftover tiles served via atomic counter
#define NEG_INF_F (-1e30f)
#define POS_INF_F ( 1e30f)
#define MARGIN_F  0.2f

// smem layout (dynamic): A | B0 | B1 | sRow ; sCol aliases B[p]
#define AB_BYTES   (BM * SH * 2)                   // 34816
#define B_OFF(p)   (AB_BYTES + (p) * AB_BYTES)
#define SROW_OFF   (3 * AB_BYTES)                  // 104448
#define SMEM_TOTAL (SROW_OFF + 8 * BM * 8)         // 112640

// ---------------- device-global state ----------------
__device__ unsigned       g_max_enc[B_ROWS];
__device__ unsigned       g_min_enc[B_ROWS];
__device__ __nv_bfloat16  g_im_bf16[B_ROWS * DIM];   // 2 MB, L2-resident
__device__ int            g_ids32[B_ROWS];
__device__ int            g_extra = 0;               // tail-tile counter (self-resetting)
__device__ int            g_done  = 0;               // CTA completion counter (self-resetting)

__device__ __forceinline__ unsigned enc_f(float f) {
    unsigned u = __float_as_uint(f);
    return (u & 0x80000000u) ? ~u : (u | 0x80000000u);
}
__device__ __forceinline__ float dec_f(unsigned u) {
    return __uint_as_float((u & 0x80000000u) ? (u & 0x7FFFFFFFu) : ~u);
}
__device__ __forceinline__ uint32_t smem_u32(const void* p) {
    uint32_t a;
    asm("{ .reg .u64 t; cvta.to.shared.u64 t, %1; cvt.u32.u64 %0, t; }" : "=r"(a) : "l"(p));
    return a;
}
// lexicographic upper-triangle coords: S(b) = 64b - b(b-1)/2
__device__ __forceinline__ void tile_coords(int t, int& bi, int& bj) {
    int b = (int)((129.0f - sqrtf(16641.0f - 8.0f * (float)t)) * 0.5f);
    if (b < 0) b = 0;
    if (b > 63) b = 63;
    while (b > 0 && 64 * b - b * (b - 1) / 2 > t) --b;
    while (64 * (b + 1) - (b + 1) * b / 2 <= t) ++b;
    bi = b;
    bj = b + (t - (64 * b - b * (b - 1) / 2));
}
#define LDSM_X4(r0, r1, r2, r3, addr) \
    asm volatile("ldmatrix.sync.aligned.m8n8.x4.shared.b16 {%0,%1,%2,%3}, [%4];" \
                 : "=r"(r0), "=r"(r1), "=r"(r2), "=r"(r3) : "r"(addr))
#define CP_ASYNC16(dst, src) \
    asm volatile("cp.async.cg.shared.global [%0], [%1], 16;" :: "r"(dst), "l"(src))
#define CP_COMMIT() asm volatile("cp.async.commit_group;" ::: "memory")
#define CP_WAIT0()  asm volatile("cp.async.wait_group 0;" ::: "memory")

// ---------------------------------------------------------------------------
// Kernel 1: convert im -> bf16, ids -> int32, clear reductions (as R12).
// ---------------------------------------------------------------------------
__global__ void convert_kernel(const float* __restrict__ im, const void* __restrict__ ids) {
    __shared__ int s_is64;
    const int tid = blockIdx.x * blockDim.x + threadIdx.x;   // 65536

    if (blockIdx.x < 32) {
        if (threadIdx.x < 32) {
            const unsigned* w = (const unsigned*)ids;
            unsigned v = w[2 * threadIdx.x + 1] | w[2 * threadIdx.x + 65];
            unsigned any = __ballot_sync(0xffffffffu, v != 0u);
            if (threadIdx.x == 0) s_is64 = (any == 0u) ? 1 : 0;
        }
        __syncthreads();
        g_max_enc[tid] = enc_f(NEG_INF_F);
        g_min_enc[tid] = enc_f(POS_INF_F);
        g_ids32[tid] = s_is64 ? (int)((const long long*)ids)[tid]
                              : ((const int*)ids)[tid];
    }
    const float4* in4 = (const float4*)im;
    float4 v0 = in4[tid];
    float4 v1 = in4[tid + 65536];
    float4 v2 = in4[tid + 131072];
    float4 v3 = in4[tid + 196608];
    __nv_bfloat162* o = (__nv_bfloat162*)g_im_bf16;
    o[2 * tid + 0]            = __floats2bfloat162_rn(v0.x, v0.y);
    o[2 * tid + 1]            = __floats2bfloat162_rn(v0.z, v0.w);
    o[2 * (tid + 65536) + 0]  = __floats2bfloat162_rn(v1.x, v1.y);
    o[2 * (tid + 65536) + 1]  = __floats2bfloat162_rn(v1.z, v1.w);
    o[2 * (tid + 131072) + 0] = __floats2bfloat162_rn(v2.x, v2.y);
    o[2 * (tid + 131072) + 1] = __floats2bfloat162_rn(v2.z, v2.w);
    o[2 * (tid + 196608) + 0] = __floats2bfloat162_rn(v3.x, v3.y);
    o[2 * (tid + 196608) + 1] = __floats2bfloat162_rn(v3.z, v3.w);
}

// ---------------------------------------------------------------------------
// Kernel 2: persistent tiles. Static 6-tile chunks with A-reuse and
// double-buffered B prefetch; 256 leftover tiles grabbed dynamically
// (early-grab keeps prefetch overlap). 3 barriers/tile (4th proven redundant).
// ---------------------------------------------------------------------------
__global__ void __launch_bounds__(256, 2)
tile_kernel(void) {
    extern __shared__ char smem[];
    __shared__ int s_idr[BM], s_idc[BM];
    __shared__ int s_next;
    const int tid = threadIdx.x;
    const uint32_t smem_base = smem_u32(smem);

    const int t0 = blockIdx.x * CHUNK;
    const int t1 = t0 + CHUNK;

    int bi, bj;
    tile_coords(t0, bi, bj);

#define STAGE(dstoff, row0) do {                                              \
        uint32_t _d = smem_base + (dstoff);                                   \
        const char* _s = (const char*)(g_im_bf16 + (size_t)(row0) * DIM);     \
        _Pragma("unroll")                                                     \
        for (int _it = 0; _it < 8; ++_it) {                                   \
            int _idx = _it * 256 + tid;                                       \
            int _row = _idx >> 4, _q = _idx & 15;                             \
            CP_ASYNC16(_d + _row * (SH * 2) + _q * 16, _s + _row * 256 + _q * 16); \
        } } while (0)

    STAGE(0, bi * BM);          // A
    STAGE(B_OFF(0), bj * BM);   // B(t0)
    CP_COMMIT();

    const int warp = tid >> 5, lane = tid & 31;
    const int wm = warp >> 1, wn = warp & 1;
    const int g = lane >> 2, tig = lane & 3;
    const int grp = lane >> 3, rin = lane & 7;

    uint32_t aaddr[2];
#pragma unroll
    for (int mt = 0; mt < 2; ++mt)
        aaddr[mt] = smem_base + 2 * ((wm * 32 + mt * 16 + (grp & 1) * 8 + rin) * SH + (grp >> 1) * 8);

    int t = t0;
    int p = 0;
    for (;;) {
        const int m0 = bi * BM, n0 = bj * BM;
        const bool diag = (bi == bj);
        const bool grabbing = (t >= t1 - 1);     // last static tile, or an extra

        if (grabbing && tid == 0) s_next = atomicAdd(&g_extra, 1);
        CP_WAIT0();                              // tile data landed
        if (tid < BM) {
            s_idr[tid] = g_ids32[m0 + tid];
            s_idc[tid] = g_ids32[n0 + tid];
        }
        __syncthreads();                         // (1) ids + s_next + staged data visible

        int tn;                                  // next tile (-1 = none)
        if (!grabbing)            tn = t + 1;
        else if (s_next < NEXTRA) tn = TEXTRA + s_next;
        else                      tn = -1;

        const uint32_t Bs32 = smem_base + B_OFF(p);
        uint32_t baddr[4];
#pragma unroll
        for (int q = 0; q < 4; ++q)
            baddr[q] = Bs32 + 2 * ((wn * 64 + 16 * q + (grp >> 1) * 8 + rin) * SH + (grp & 1) * 8);

        float acc[2][8][4];
#pragma unroll
        for (int mt = 0; mt < 2; ++mt)
#pragma unroll
            for (int nt = 0; nt < 8; ++nt)
#pragma unroll
                for (int r = 0; r < 4; ++r) acc[mt][nt][r] = 0.0f;

#pragma unroll
        for (int ks = 0; ks < 8; ++ks) {
            const uint32_t koff = ks * 32;
            unsigned a[2][4], b[8][2];
#pragma unroll
            for (int mt = 0; mt < 2; ++mt)
                LDSM_X4(a[mt][0], a[mt][1], a[mt][2], a[mt][3], aaddr[mt] + koff);
#pragma unroll
            for (int q = 0; q < 4; ++q)
                LDSM_X4(b[2 * q][0], b[2 * q][1], b[2 * q + 1][0], b[2 * q + 1][1], baddr[q] + koff);
#pragma unroll
            for (int mt = 0; mt < 2; ++mt)
#pragma unroll
                for (int nt = 0; nt < 8; ++nt) {
                    asm volatile(
                        "mma.sync.aligned.m16n8k16.row.col.f32.bf16.bf16.f32 "
                        "{%0,%1,%2,%3}, {%4,%5,%6,%7}, {%8,%9}, {%0,%1,%2,%3};"
                        : "+f"(acc[mt][nt][0]), "+f"(acc[mt][nt][1]),
                          "+f"(acc[mt][nt][2]), "+f"(acc[mt][nt][3])
                        : "r"(a[mt][0]), "r"(a[mt][1]), "r"(a[mt][2]), "r"(a[mt][3]),
                          "r"(b[nt][0]), "r"(b[nt][1]));
                }
        }
        __syncthreads();                         // (2) done reading A and B[p]

        // prefetch next tile (A only when its row changes — reuse otherwise)
        int nbi = bi, nbj = bj;
        if (tn >= 0) {
            tile_coords(tn, nbi, nbj);
            if (nbi != bi) STAGE(0, nbi * BM);
            STAGE(B_OFF(1 - p), nbj * BM);
            CP_COMMIT();
        }

        // ---- register-pooled epilogue (exact R12 math); sCol aliases B[p] ----
        float2* sRow = (float2*)(smem + SROW_OFF);
        float2* sCol = (float2*)(smem + B_OFF(p));

        int rids[4];
#pragma unroll
        for (int mt = 0; mt < 2; ++mt)
#pragma unroll
            for (int half = 0; half < 2; ++half)
                rids[mt * 2 + half] = s_idr[wm * 32 + mt * 16 + g + half * 8];

        float rmin[4] = {POS_INF_F, POS_INF_F, POS_INF_F, POS_INF_F};
        float rmax[4] = {NEG_INF_F, NEG_INF_F, NEG_INF_F, NEG_INF_F};

#pragma unroll
        for (int ph = 0; ph < 2; ++ph) {
            float cmin[8], cmax[8];
            int cids[8];
#pragma unroll
            for (int i = 0; i < 8; ++i) {
                cmin[i] = POS_INF_F; cmax[i] = NEG_INF_F;
                int nt = ph * 4 + (i >> 1);
                cids[i] = s_idc[wn * 64 + nt * 8 + 2 * tig + (i & 1)];
            }
#pragma unroll
            for (int i = 0; i < 8; ++i) {
                const int nt = ph * 4 + (i >> 1), e = i & 1;
                const int lc = wn * 64 + nt * 8 + 2 * tig + e;
                const int cid = cids[i];
#pragma unroll
                for (int mt = 0; mt < 2; ++mt)
#pragma unroll
                    for (int half = 0; half < 2; ++half) {
                        const int ri = mt * 2 + half;
                        float s = acc[mt][nt][half * 2 + e];
                        if (diag && (wm * 32 + mt * 16 + g + half * 8) == lc) s = 0.0f;
                        if (rids[ri] == cid) {
                            rmin[ri] = fminf(rmin[ri], s);
                            cmin[i]  = fminf(cmin[i], s);
                        } else {
                            rmax[ri] = fmaxf(rmax[ri], s);
                            cmax[i]  = fmaxf(cmax[i], s);
                        }
                    }
            }
            if (!diag) {
                const int slot = wm * 8 + g;
#pragma unroll
                for (int i = 0; i < 8; ++i) {
                    const int nt = ph * 4 + (i >> 1);
                    const int lc = wn * 64 + nt * 8 + 2 * tig + (i & 1);
                    sCol[slot * BM + lc] = make_float2(cmin[i], cmax[i]);
                }
            }
        }
        {
            const int slot = wn * 4 + tig;
#pragma unroll
            for (int ri = 0; ri < 4; ++ri) {
                const int lr = wm * 32 + (ri >> 1) * 16 + g + (ri & 1) * 8;
                sRow[slot * BM + lr] = make_float2(rmin[ri], rmax[ri]);
            }
        }
        __syncthreads();                         // (3) partials complete

        if (tid < BM) {
            float vmin = POS_INF_F, vmax = NEG_INF_F;
#pragma unroll
            for (int s = 0; s < 8; ++s) {
                float2 q = sRow[s * BM + tid];
                vmin = fminf(vmin, q.x);
                vmax = fmaxf(vmax, q.y);
            }
            atomicMax(&g_max_enc[m0 + tid], enc_f(vmax));
            atomicMin(&g_min_enc[m0 + tid], enc_f(vmin));
        } else if (!diag) {
            const int c = tid - BM;
            float vmin = POS_INF_F, vmax = NEG_INF_F;
#pragma unroll
            for (int s = 0; s < 32; ++s) {
                float2 q = sCol[s * BM + c];
                vmin = fminf(vmin, q.x);
                vmax = fmaxf(vmax, q.y);
            }
            atomicMax(&g_max_enc[n0 + c], enc_f(vmax));
            atomicMin(&g_min_enc[n0 + c], enc_f(vmin));
        }
        // NOTE: no 4th barrier. All hazards (s_idr/idc rewrite, s_next rewrite,
        // sCol=B[p] reads vs next prefetch into B[p]) are ordered by barriers
        // (1)/(2) of the NEXT iteration: combine reads precede each thread's
        // next sync(1); conflicting writes occur only after sync(1)/sync(2).

        if (tn < 0) break;
        t = tn; bi = nbi; bj = nbj; p ^= 1;
    }
#undef STAGE

    // self-reset scheduler state for next graph replay (deterministic)
    if (tid == 0) {
        if (atomicAdd(&g_done, 1) == NCTA - 1) {
            g_extra = 0;
            g_done = 0;
        }
    }
}

// ---------------------------------------------------------------------------
// Kernel 3: deterministic scalar reduction of the hinge loss.
// ---------------------------------------------------------------------------
__global__ void finalize_kernel(float* __restrict__ out) {
    __shared__ float part[1024];
    float s = 0.0f;
    for (int i = threadIdx.x; i < B_ROWS; i += 1024) {
        s += fmaxf(MARGIN_F + dec_f(g_max_enc[i]) - dec_f(g_min_enc[i]), 0.0f);
    }
    part[threadIdx.x] = s;
    __syncthreads();
    for (int o = 512; o; o >>= 1) {
        if (threadIdx.x < o) part[threadIdx.x] += part[threadIdx.x + o];
        __syncthreads();
    }
    if (threadIdx.x == 0) out[0] = part[0];
}

extern "C" void kernel_launch(void* const* d_in, const int* in_sizes, int n_in,
                              void* d_out, int out_size) {
    const float* im  = (const float*)d_in[0];
    const void*  ids = d_in[1];

    cudaFuncSetAttribute(tile_kernel, cudaFuncAttributeMaxDynamicSharedMemorySize, SMEM_TOTAL);

    convert_kernel<<<256, 256>>>(im, ids);
    tile_kernel<<<NCTA, 256, SMEM_TOTAL>>>();
    finalize_kernel<<<1, 1024>>>((float*)d_out);
}